// round 2
// baseline (speedup 1.0000x reference)
#include <cuda_runtime.h>
#include <math_constants.h>

#define NF 8
#define NQ 300
#define HH 96
#define WW 96
#define HW (HH*WW)        // 9216
#define FHW (NF*HW)       // 73728
#define ALPHA_C 0.25f
#define EPSV 1e-8f

// Per-batch target precomputations (no allocation allowed -> device globals)
__device__ float g_tgtx[2][NF*HH];       // max over w per (f,h)
__device__ float g_tgty[2][NF*WW];       // max over h per (f,w)
__device__ float g_partial[16][3];       // per (b,f): [tsum, sum(tgtx), sum(tgty)]
__device__ unsigned g_tbits[16][HH*3];   // packed binary tmask: word (h*3 + w/32)

__device__ __forceinline__ float sigmoid_fast(float x) {
    float a = fabsf(x);
    float u = __expf(-a);
    float r = __fdividef(1.0f, 1.0f + u);
    return (x >= 0.0f) ? r : u * r;
}

__device__ __forceinline__ float warp_sum(float v) {
    #pragma unroll
    for (int o = 16; o; o >>= 1) v += __shfl_xor_sync(0xffffffff, v, o);
    return v;
}

// orderable-uint encoding for float max via redux.sync.max.u32
__device__ __forceinline__ unsigned fkey(float x) {
    int b = __float_as_int(x);
    return (unsigned)b ^ ((unsigned)(b >> 31) | 0x80000000u);
}
__device__ __forceinline__ float fkey_inv(unsigned k) {
    int b = (k & 0x80000000u) ? (int)(k ^ 0x80000000u) : (int)~k;
    return __int_as_float(b);
}

// ---------------------------------------------------------------------------
// Prep: one block per (b,f) frame. 96 threads.
// ---------------------------------------------------------------------------
__global__ __launch_bounds__(96) void prep_kernel(const float* __restrict__ tmask) {
    int bf = blockIdx.x;            // 0..15
    int b = bf >> 3, f = bf & 7;
    int tid = threadIdx.x;          // 0..95
    const float* base = tmask + (size_t)bf * HW;

    // row scan (thread = row h): rowmax, rowsum, packed bits
    const float* row = base + tid * WW;
    float rmax = -CUDART_INF_F, rsum = 0.0f;
    unsigned bits[3] = {0u, 0u, 0u};
    #pragma unroll 8
    for (int w = 0; w < WW; ++w) {
        float v = row[w];
        rmax = fmaxf(rmax, v);
        rsum += v;
        if (v != 0.0f) bits[w >> 5] |= (1u << (w & 31));
    }
    g_tgtx[b][f * HH + tid] = rmax;
    g_tbits[bf][tid * 3 + 0] = bits[0];
    g_tbits[bf][tid * 3 + 1] = bits[1];
    g_tbits[bf][tid * 3 + 2] = bits[2];

    // col scan (thread = column w)
    float cmax = -CUDART_INF_F;
    #pragma unroll 8
    for (int h = 0; h < HH; ++h) cmax = fmaxf(cmax, base[h * WW + tid]);
    g_tgty[b][f * WW + tid] = cmax;

    // block reduce (3 warps)
    __shared__ float red[3][3];
    float s0 = warp_sum(rsum);
    float s1 = warp_sum(rmax);
    float s2 = warp_sum(cmax);
    int wid = tid >> 5, lane = tid & 31;
    if (lane == 0) { red[wid][0] = s0; red[wid][1] = s1; red[wid][2] = s2; }
    __syncthreads();
    if (tid == 0) {
        g_partial[bf][0] = red[0][0] + red[1][0] + red[2][0];
        g_partial[bf][1] = red[0][1] + red[1][1] + red[2][1];
        g_partial[bf][2] = red[0][2] + red[1][2] + red[2][2];
    }
}

// ---------------------------------------------------------------------------
// Main cost kernel: one block per (b, q). block = 384 = 4 x 96
// thread tid: fixed column w0 = tid%96, rows h0 + 4k, h0 = tid/96
// ---------------------------------------------------------------------------
__global__ __launch_bounds__(384) void cost_kernel(
    const float* __restrict__ logits,   // (2,8,300,1)
    const float* __restrict__ boxes,    // (2,8,300,4)
    const float* __restrict__ masks,    // (2,8,300,96,96)
    const float* __restrict__ tbox,     // (2,8,4)
    const int*   __restrict__ tvalid,   // (2,8)
    const unsigned char* __restrict__ vpad, // (2,96,96) bool
    float* __restrict__ C)              // (2,300)
{
    int blk = blockIdx.x;
    int b = blk / NQ, q = blk % NQ;
    int tid = threadIdx.x;
    int w0 = tid % WW;
    int h0 = tid / WW;                  // 0..3
    int warp = tid >> 5, lane = tid & 31;
    int c = warp % 3;                   // word index within row (w0>>5, uniform per warp)
    bool lead = (lane == 0);

    __shared__ float rowAll[NF * HH * 3];       // per-warp row-max partials
    __shared__ float cmAll[NF * 4 * WW];        // per-(f,h0) column-max partials
    __shared__ float red[12][7];

    // vpad bits: invariant across f -> one 24-bit register mask
    const unsigned char* vb = vpad + (size_t)b * HW;
    unsigned padbits = 0;
    #pragma unroll
    for (int k = 0; k < 24; ++k)
        if (vb[(h0 + 4 * k) * WW + w0]) padbits |= (1u << k);

    float facc = 0.0f, nacc = 0.0f, sacc = 0.0f;

    for (int f = 0; f < NF; ++f) {
        const float* mb = masks + (size_t)((b * NF + f) * NQ + q) * HW;
        const unsigned* tw = g_tbits[b * NF + f];
        float cm = -CUDART_INF_F;
        #pragma unroll 8
        for (int k = 0; k < 24; ++k) {
            int h = h0 + 4 * k;
            float x = mb[h * WW + w0];
            if (padbits & (1u << k)) x = 0.0f;
            bool tb = (tw[h * 3 + c] >> lane) & 1;   // broadcast word per warp

            float u = __expf(-fabsf(x));             // exp(-|x|)
            float onep = 1.0f + u;
            float r = __fdividef(1.0f, onep);        // sigmoid(|x|)
            float p = (x >= 0.0f) ? r : u * r;       // sigmoid(x)
            float lg = __logf(onep);                 // log1p(exp(-|x|))
            float mx = fmaxf(x, 0.0f);
            float ce = mx - (tb ? x : 0.0f) + lg;
            float omp = tb ? (1.0f - p) : p;         // 1 - p_t
            float at = tb ? 0.25f : 0.75f;           // alpha_t
            facc = fmaf(at * ce * omp, omp, facc);
            if (tb) nacc += p;
            sacc += p;

            cm = fmaxf(cm, x);
            unsigned mk;
            asm("redux.sync.max.u32 %0, %1, 0xffffffff;" : "=r"(mk) : "r"(fkey(x)));
            if (lead) rowAll[(f * HH + h) * 3 + c] = fkey_inv(mk);
        }
        cmAll[(f * 4 + h0) * WW + w0] = cm;
    }
    __syncthreads();

    // projection dice partials: 768 rows + 768 cols, 2 per thread
    float sx = 0, nx = 0, sy = 0, ny = 0;
    #pragma unroll
    for (int j = tid; j < NF * HH; j += 384) {
        float rm = fmaxf(fmaxf(rowAll[j * 3], rowAll[j * 3 + 1]), rowAll[j * 3 + 2]);
        float px = sigmoid_fast(rm);
        sx += px; nx += px * g_tgtx[b][j];
        int f = j / WW, w = j % WW;
        float c0 = fmaxf(cmAll[(f * 4 + 0) * WW + w], cmAll[(f * 4 + 1) * WW + w]);
        float c1 = fmaxf(cmAll[(f * 4 + 2) * WW + w], cmAll[(f * 4 + 3) * WW + w]);
        float py = sigmoid_fast(fmaxf(c0, c1));
        sy += py; ny += py * g_tgty[b][j];
    }

    // block reduce 7 accumulators
    float v0 = warp_sum(facc), v1 = warp_sum(nacc), v2 = warp_sum(sacc);
    float v3 = warp_sum(sx),   v4 = warp_sum(nx);
    float v5 = warp_sum(sy),   v6 = warp_sum(ny);
    if (lead) {
        red[warp][0] = v0; red[warp][1] = v1; red[warp][2] = v2;
        red[warp][3] = v3; red[warp][4] = v4; red[warp][5] = v5; red[warp][6] = v6;
    }
    __syncthreads();

    if (tid == 0) {
        float t0=0,t1=0,t2=0,t3=0,t4=0,t5=0,t6=0;
        #pragma unroll
        for (int i = 0; i < 12; ++i) {
            t0 += red[i][0]; t1 += red[i][1]; t2 += red[i][2];
            t3 += red[i][3]; t4 += red[i][4]; t5 += red[i][5]; t6 += red[i][6];
        }
        float tsum = 0, txs = 0, tys = 0;
        #pragma unroll
        for (int f = 0; f < NF; ++f) {
            tsum += g_partial[b * NF + f][0];
            txs  += g_partial[b * NF + f][1];
            tys  += g_partial[b * NF + f][2];
        }
        float cost_mask = t0 / (float)FHW;
        float cost_dice = -((2.0f * t1 + 1.0f) / (t2 + tsum + 1.0f));
        float dx = (2.0f * t4 + 1.0f) / (t3 + txs + 1.0f);
        float dy = (2.0f * t6 + 1.0f) / (t5 + tys + 1.0f);
        float cost_proj = -0.5f * (dy + dx);

        float cls = 0, wsum = 0, bbox = 0, giou = 0;
        #pragma unroll
        for (int f = 0; f < NF; ++f) {
            float lg = logits[(b * NF + f) * NQ + q];
            float p = sigmoid_fast(lg);
            float neg = (1.0f - ALPHA_C) * p * p * (-__logf(1.0f - p + EPSV));
            float pos = ALPHA_C * (1.0f - p) * (1.0f - p) * (-__logf(p + EPSV));
            float wv = (tvalid[b * NF + f] != 0) ? 1.0f : 0.0f;
            cls += (pos - neg) * wv; wsum += wv;

            const float* bx = boxes + (size_t)((b * NF + f) * NQ + q) * 4;
            const float* tx = tbox + (size_t)(b * NF + f) * 4;
            bbox += fabsf(bx[0]-tx[0]) + fabsf(bx[1]-tx[1]) + fabsf(bx[2]-tx[2]) + fabsf(bx[3]-tx[3]);

            float sx0 = bx[0]-0.5f*bx[2], sy0 = bx[1]-0.5f*bx[3];
            float sx1 = bx[0]+0.5f*bx[2], sy1 = bx[1]+0.5f*bx[3];
            float tx0 = tx[0]-0.5f*tx[2], ty0 = tx[1]-0.5f*tx[3];
            float tx1 = tx[0]+0.5f*tx[2], ty1 = tx[1]+0.5f*tx[3];
            float a1 = (sx1-sx0)*(sy1-sy0);
            float a2 = (tx1-tx0)*(ty1-ty0);
            float iw = fmaxf(fminf(sx1,tx1) - fmaxf(sx0,tx0), 0.0f);
            float ih = fmaxf(fminf(sy1,ty1) - fmaxf(sy0,ty0), 0.0f);
            float inter = iw * ih;
            float uni = a1 + a2 - inter;
            float iou = inter / uni;
            float cw = fmaxf(fmaxf(sx1,tx1) - fminf(sx0,tx0), 0.0f);
            float ch = fmaxf(fmaxf(sy1,ty1) - fminf(sy0,ty0), 0.0f);
            float ac = cw * ch;
            giou += -(iou - (ac - uni) / ac);
        }
        float cost_class = cls / wsum;
        float cost_bbox  = bbox * (1.0f / NF);
        float cost_giou  = giou * (1.0f / NF);

        C[b * NQ + q] = cost_class + cost_bbox + cost_giou + cost_mask + cost_dice + cost_proj;
    }
}

// ---------------------------------------------------------------------------
// Argmin over queries per batch + tail writes. grid=2, block=256
// ---------------------------------------------------------------------------
__global__ void argmin_kernel(const float* __restrict__ C, float* __restrict__ out, int out_size) {
    int b = blockIdx.x;
    int tid = threadIdx.x;
    float best = CUDART_INF_F; int bi = NQ;
    for (int q = tid; q < NQ; q += blockDim.x) {
        float v = C[b * NQ + q];
        if (v < best || (v == best && q < bi)) { best = v; bi = q; }
    }
    #pragma unroll
    for (int o = 16; o; o >>= 1) {
        float ov = __shfl_down_sync(0xffffffff, best, o);
        int   oi = __shfl_down_sync(0xffffffff, bi,   o);
        if (ov < best || (ov == best && oi < bi)) { best = ov; bi = oi; }
    }
    __shared__ float sv[8]; __shared__ int si[8];
    int wid = tid >> 5, lane = tid & 31;
    if (lane == 0) { sv[wid] = best; si[wid] = bi; }
    __syncthreads();
    if (tid == 0) {
        int nw = blockDim.x >> 5;
        for (int i = 1; i < nw; ++i) {
            if (sv[i] < best || (sv[i] == best && si[i] < bi)) { best = sv[i]; bi = si[i]; }
        }
        if (out_size >= 608) {
            long long* op = (long long*)(out + 600);
            op[b] = (long long)bi;
            op[2 + b] = 0ll;
            if (b == 0) for (int i = 608; i < out_size; ++i) out[i] = 0.0f;
        } else if (out_size >= 604) {
            out[600 + b] = (float)bi;
            out[602 + b] = 0.0f;
            if (b == 0) for (int i = 604; i < out_size; ++i) out[i] = 0.0f;
        } else {
            if (b == 0) for (int i = 600; i < out_size; ++i) out[i] = 0.0f;
        }
    }
}

extern "C" void kernel_launch(void* const* d_in, const int* in_sizes, int n_in,
                              void* d_out, int out_size) {
    const float* logits = (const float*)d_in[0];
    const float* boxes  = (const float*)d_in[1];
    const float* masks  = (const float*)d_in[2];
    const float* tmask  = (const float*)d_in[3];
    const float* tbox   = (const float*)d_in[4];
    const int*   tvalid = (const int*)d_in[5];
    const unsigned char* vpad = (const unsigned char*)d_in[6];
    float* out = (float*)d_out;

    prep_kernel<<<16, 96>>>(tmask);
    cost_kernel<<<2 * NQ, 384>>>(logits, boxes, masks, tbox, tvalid, vpad, out);
    argmin_kernel<<<2, 256>>>(out, out, out_size);
}

// round 3
// speedup vs baseline: 2.1307x; 2.1307x over previous
#include <cuda_runtime.h>
#include <math_constants.h>

#define NF 8
#define NQ 300
#define HH 96
#define WW 96
#define HW (HH*WW)        // 9216
#define FHW (NF*HW)       // 73728
#define ALPHA_C 0.25f
#define EPSV 1e-8f

// Per-batch target precomputations (no allocation allowed -> device globals)
__device__ float g_tgtx[2][NF*HH];     // max over w per (f,h)
__device__ float g_tgty[2][NF*WW];     // max over h per (f,w)
__device__ float g_partial[16][3];     // per (b,f): [tsum, sum(tgtx), sum(tgty)]
__device__ uint2 g_meta[16][HH*3];     // per (b,f,row,chunk): {tmask bits, vpad bits}

__device__ __forceinline__ float sigmoid_fast(float x) {
    float a = fabsf(x);
    float u = __expf(-a);
    float r = __fdividef(1.0f, 1.0f + u);
    return (x >= 0.0f) ? r : u * r;
}

__device__ __forceinline__ float warp_sum(float v) {
    #pragma unroll
    for (int o = 16; o; o >>= 1) v += __shfl_xor_sync(0xffffffff, v, o);
    return v;
}
__device__ __forceinline__ float warp_max(float v) {
    #pragma unroll
    for (int o = 16; o; o >>= 1) v = fmaxf(v, __shfl_xor_sync(0xffffffff, v, o));
    return v;
}

// ---------------------------------------------------------------------------
// Prep: one block per (b,f). 256 threads = 8 warps; warp owns 12 rows.
// Packs tmask+vpad bits, computes target row/col maxes and sums.
// ---------------------------------------------------------------------------
__global__ __launch_bounds__(256) void prep_kernel(
    const float* __restrict__ tmask, const unsigned char* __restrict__ vpad)
{
    int bf = blockIdx.x;            // 0..15
    int b = bf >> 3, f = bf & 7;
    int tid = threadIdx.x;
    int wp = tid >> 5, lane = tid & 31;
    const float* base = tmask + (size_t)bf * HW;
    const unsigned char* vb = vpad + (size_t)b * HW;

    __shared__ float colPart[8][3][32];
    __shared__ float warpRM[8];     // per-warp sum of row maxes
    __shared__ float warpTS[8];     // per-warp sum of elements
    __shared__ float colFinal[96];

    float cm0 = -CUDART_INF_F, cm1 = -CUDART_INF_F, cm2 = -CUDART_INF_F;
    float rm_sum = 0.0f, t_sum = 0.0f;

    #pragma unroll 4
    for (int r = 0; r < 12; ++r) {
        int row = wp * 12 + r;
        const float* rp = base + row * WW;
        float v0 = rp[lane], v1 = rp[32 + lane], v2 = rp[64 + lane];
        unsigned t0 = __ballot_sync(0xffffffff, v0 != 0.0f);
        unsigned t1 = __ballot_sync(0xffffffff, v1 != 0.0f);
        unsigned t2 = __ballot_sync(0xffffffff, v2 != 0.0f);
        const unsigned char* vr = vb + row * WW;
        unsigned p0 = __ballot_sync(0xffffffff, vr[lane] != 0);
        unsigned p1 = __ballot_sync(0xffffffff, vr[32 + lane] != 0);
        unsigned p2 = __ballot_sync(0xffffffff, vr[64 + lane] != 0);
        if (lane == 0) {
            g_meta[bf][row * 3 + 0] = make_uint2(t0, p0);
            g_meta[bf][row * 3 + 1] = make_uint2(t1, p1);
            g_meta[bf][row * 3 + 2] = make_uint2(t2, p2);
        }
        float rm = warp_max(fmaxf(fmaxf(v0, v1), v2));
        if (lane == 0) { g_tgtx[b][f * HH + row] = rm; rm_sum += rm; }
        t_sum += v0 + v1 + v2;
        cm0 = fmaxf(cm0, v0); cm1 = fmaxf(cm1, v1); cm2 = fmaxf(cm2, v2);
    }
    colPart[wp][0][lane] = cm0;
    colPart[wp][1][lane] = cm1;
    colPart[wp][2][lane] = cm2;
    float ts = warp_sum(t_sum);
    if (lane == 0) { warpTS[wp] = ts; warpRM[wp] = rm_sum; }
    __syncthreads();

    if (tid < 96) {
        int c = tid >> 5, l = tid & 31;
        float m = -CUDART_INF_F;
        #pragma unroll
        for (int w = 0; w < 8; ++w) m = fmaxf(m, colPart[w][c][l]);
        g_tgty[b][f * WW + tid] = m;
        colFinal[tid] = m;
    }
    __syncthreads();
    if (tid == 0) {
        float tsum = 0, txs = 0, tys = 0;
        #pragma unroll
        for (int i = 0; i < 8; ++i) { tsum += warpTS[i]; txs += warpRM[i]; }
        for (int i = 0; i < 96; ++i) tys += colFinal[i];
        g_partial[bf][0] = tsum; g_partial[bf][1] = txs; g_partial[bf][2] = tys;
    }
}

// ---------------------------------------------------------------------------
// Main cost kernel: one block per (b, q). 384 threads = 12 warps.
// Warp wp owns rows 8*wp .. 8*wp+7 of every frame.
// Lane l covers columns {l, 32+l, 64+l}.
// ---------------------------------------------------------------------------
__global__ __launch_bounds__(384, 4) void cost_kernel(
    const float* __restrict__ logits,   // (2,8,300,1)
    const float* __restrict__ boxes,    // (2,8,300,4)
    const float* __restrict__ masks,    // (2,8,300,96,96)
    const float* __restrict__ tbox,     // (2,8,4)
    const int*   __restrict__ tvalid,   // (2,8)
    float* __restrict__ C)              // (2,300)
{
    int blk = blockIdx.x;
    int b = blk / NQ, q = blk % NQ;
    int tid = threadIdx.x;
    int warp = tid >> 5, lane = tid & 31;

    __shared__ float rowFinal[NF * HH];           // 3 KB
    __shared__ float colAll[NF * 3 * 384];        // 36 KB: [f][chunk][warp][lane]
    __shared__ float red[12][7];

    float facc = 0.0f, nacc = 0.0f, sacc = 0.0f;

    for (int f = 0; f < NF; ++f) {
        const float* mb = masks + (size_t)((b * NF + f) * NQ + q) * HW;
        const uint2* mt = g_meta[b * NF + f];
        float c0 = -CUDART_INF_F, c1 = -CUDART_INF_F, c2 = -CUDART_INF_F;
        #pragma unroll 4
        for (int r = 0; r < 8; ++r) {
            int row = warp * 8 + r;
            uint2 m0 = mt[row * 3 + 0];
            uint2 m1 = mt[row * 3 + 1];
            uint2 m2 = mt[row * 3 + 2];
            const float* rp = mb + row * WW;
            float x0 = rp[lane], x1 = rp[32 + lane], x2 = rp[64 + lane];
            if ((m0.y >> lane) & 1) x0 = 0.0f;
            if ((m1.y >> lane) & 1) x1 = 0.0f;
            if ((m2.y >> lane) & 1) x2 = 0.0f;
            bool t0 = (m0.x >> lane) & 1;
            bool t1 = (m1.x >> lane) & 1;
            bool t2 = (m2.x >> lane) & 1;

            #pragma unroll
            for (int c = 0; c < 3; ++c) {
                float x = (c == 0) ? x0 : (c == 1) ? x1 : x2;
                bool tb = (c == 0) ? t0 : (c == 1) ? t1 : t2;
                float u = __expf(-fabsf(x));
                float onep = 1.0f + u;
                float rr = __fdividef(1.0f, onep);
                float p = (x >= 0.0f) ? rr : u * rr;
                float lg = __logf(onep);
                float ce = fmaxf(x, 0.0f) - (tb ? x : 0.0f) + lg;
                float omp = tb ? (1.0f - p) : p;
                float at = tb ? 0.25f : 0.75f;
                facc = fmaf(at * ce * omp, omp, facc);
                sacc += p;
                if (tb) nacc += p;
            }
            c0 = fmaxf(c0, x0); c1 = fmaxf(c1, x1); c2 = fmaxf(c2, x2);
            float rm = warp_max(fmaxf(fmaxf(x0, x1), x2));
            if (lane == 0) rowFinal[f * HH + row] = rm;
        }
        colAll[((f * 3 + 0) * 12 + warp) * 32 + lane] = c0;
        colAll[((f * 3 + 1) * 12 + warp) * 32 + lane] = c1;
        colAll[((f * 3 + 2) * 12 + warp) * 32 + lane] = c2;
    }
    __syncthreads();

    // projection dice partials: 768 rows + 768 cols, 2 each per thread
    float sx = 0, nx = 0, sy = 0, ny = 0;
    #pragma unroll
    for (int j = tid; j < NF * HH; j += 384) {
        float px = sigmoid_fast(rowFinal[j]);
        sx += px; nx += px * g_tgtx[b][j];
        int f = j / WW, w = j % WW;
        int c = w >> 5, l = w & 31;
        const float* cp = &colAll[((f * 3 + c) * 12) * 32 + l];
        float m = cp[0];
        #pragma unroll
        for (int wp = 1; wp < 12; ++wp) m = fmaxf(m, cp[wp * 32]);
        float py = sigmoid_fast(m);
        sy += py; ny += py * g_tgty[b][j];
    }

    // block reduce 7 accumulators
    float v0 = warp_sum(facc), v1 = warp_sum(nacc), v2 = warp_sum(sacc);
    float v3 = warp_sum(sx),   v4 = warp_sum(nx);
    float v5 = warp_sum(sy),   v6 = warp_sum(ny);
    if (lane == 0) {
        red[warp][0] = v0; red[warp][1] = v1; red[warp][2] = v2;
        red[warp][3] = v3; red[warp][4] = v4; red[warp][5] = v5; red[warp][6] = v6;
    }
    __syncthreads();

    if (tid == 0) {
        float t0=0,t1=0,t2=0,t3=0,t4=0,t5=0,t6=0;
        #pragma unroll
        for (int i = 0; i < 12; ++i) {
            t0 += red[i][0]; t1 += red[i][1]; t2 += red[i][2];
            t3 += red[i][3]; t4 += red[i][4]; t5 += red[i][5]; t6 += red[i][6];
        }
        float tsum = 0, txs = 0, tys = 0;
        #pragma unroll
        for (int f = 0; f < NF; ++f) {
            tsum += g_partial[b * NF + f][0];
            txs  += g_partial[b * NF + f][1];
            tys  += g_partial[b * NF + f][2];
        }
        float cost_mask = t0 / (float)FHW;
        float cost_dice = -((2.0f * t1 + 1.0f) / (t2 + tsum + 1.0f));
        float dx = (2.0f * t4 + 1.0f) / (t3 + txs + 1.0f);
        float dy = (2.0f * t6 + 1.0f) / (t5 + tys + 1.0f);
        float cost_proj = -0.5f * (dy + dx);

        float cls = 0, wsum = 0, bbox = 0, giou = 0;
        #pragma unroll
        for (int f = 0; f < NF; ++f) {
            float lg = logits[(b * NF + f) * NQ + q];
            float p = sigmoid_fast(lg);
            float neg = (1.0f - ALPHA_C) * p * p * (-__logf(1.0f - p + EPSV));
            float pos = ALPHA_C * (1.0f - p) * (1.0f - p) * (-__logf(p + EPSV));
            float wv = (tvalid[b * NF + f] != 0) ? 1.0f : 0.0f;
            cls += (pos - neg) * wv; wsum += wv;

            const float* bx = boxes + (size_t)((b * NF + f) * NQ + q) * 4;
            const float* tx = tbox + (size_t)(b * NF + f) * 4;
            bbox += fabsf(bx[0]-tx[0]) + fabsf(bx[1]-tx[1]) + fabsf(bx[2]-tx[2]) + fabsf(bx[3]-tx[3]);

            float sx0 = bx[0]-0.5f*bx[2], sy0 = bx[1]-0.5f*bx[3];
            float sx1 = bx[0]+0.5f*bx[2], sy1 = bx[1]+0.5f*bx[3];
            float tx0 = tx[0]-0.5f*tx[2], ty0 = tx[1]-0.5f*tx[3];
            float tx1 = tx[0]+0.5f*tx[2], ty1 = tx[1]+0.5f*tx[3];
            float a1 = (sx1-sx0)*(sy1-sy0);
            float a2 = (tx1-tx0)*(ty1-ty0);
            float iw = fmaxf(fminf(sx1,tx1) - fmaxf(sx0,tx0), 0.0f);
            float ih = fmaxf(fminf(sy1,ty1) - fmaxf(sy0,ty0), 0.0f);
            float inter = iw * ih;
            float uni = a1 + a2 - inter;
            float iou = inter / uni;
            float cw = fmaxf(fmaxf(sx1,tx1) - fminf(sx0,tx0), 0.0f);
            float ch = fmaxf(fmaxf(sy1,ty1) - fminf(sy0,ty0), 0.0f);
            float ac = cw * ch;
            giou += -(iou - (ac - uni) / ac);
        }
        float cost_class = cls / wsum;
        float cost_bbox  = bbox * (1.0f / NF);
        float cost_giou  = giou * (1.0f / NF);

        C[b * NQ + q] = cost_class + cost_bbox + cost_giou + cost_mask + cost_dice + cost_proj;
    }
}

// ---------------------------------------------------------------------------
// Argmin over queries per batch + tail writes. grid=2, block=256
// ---------------------------------------------------------------------------
__global__ void argmin_kernel(const float* __restrict__ C, float* __restrict__ out, int out_size) {
    int b = blockIdx.x;
    int tid = threadIdx.x;
    float best = CUDART_INF_F; int bi = NQ;
    for (int q = tid; q < NQ; q += blockDim.x) {
        float v = C[b * NQ + q];
        if (v < best || (v == best && q < bi)) { best = v; bi = q; }
    }
    #pragma unroll
    for (int o = 16; o; o >>= 1) {
        float ov = __shfl_down_sync(0xffffffff, best, o);
        int   oi = __shfl_down_sync(0xffffffff, bi,   o);
        if (ov < best || (ov == best && oi < bi)) { best = ov; bi = oi; }
    }
    __shared__ float sv[8]; __shared__ int si[8];
    int wid = tid >> 5, lane = tid & 31;
    if (lane == 0) { sv[wid] = best; si[wid] = bi; }
    __syncthreads();
    if (tid == 0) {
        int nw = blockDim.x >> 5;
        for (int i = 1; i < nw; ++i) {
            if (sv[i] < best || (sv[i] == best && si[i] < bi)) { best = sv[i]; bi = si[i]; }
        }
        if (out_size >= 608) {
            long long* op = (long long*)(out + 600);
            op[b] = (long long)bi;
            op[2 + b] = 0ll;
            if (b == 0) for (int i = 608; i < out_size; ++i) out[i] = 0.0f;
        } else if (out_size >= 604) {
            out[600 + b] = (float)bi;
            out[602 + b] = 0.0f;
            if (b == 0) for (int i = 604; i < out_size; ++i) out[i] = 0.0f;
        } else {
            if (b == 0) for (int i = 600; i < out_size; ++i) out[i] = 0.0f;
        }
    }
}

extern "C" void kernel_launch(void* const* d_in, const int* in_sizes, int n_in,
                              void* d_out, int out_size) {
    const float* logits = (const float*)d_in[0];
    const float* boxes  = (const float*)d_in[1];
    const float* masks  = (const float*)d_in[2];
    const float* tmask  = (const float*)d_in[3];
    const float* tbox   = (const float*)d_in[4];
    const int*   tvalid = (const int*)d_in[5];
    const unsigned char* vpad = (const unsigned char*)d_in[6];
    float* out = (float*)d_out;

    prep_kernel<<<16, 256>>>(tmask, vpad);
    cost_kernel<<<2 * NQ, 384>>>(logits, boxes, masks, tbox, tvalid, out);
    argmin_kernel<<<2, 256>>>(out, out, out_size);
}

// round 4
// speedup vs baseline: 2.4022x; 1.1274x over previous
#include <cuda_runtime.h>
#include <math_constants.h>

#define NF 8
#define NQ 300
#define HH 96
#define WW 96
#define HW (HH*WW)        // 9216
#define FHW (NF*HW)       // 73728
#define ALPHA_C 0.25f
#define EPSV 1e-8f

__device__ float g_tgtx[2][NF*HH];     // max over w per (f,h)
__device__ float g_tgty[2][NF*WW];     // max over h per (f,w)
__device__ float g_partial[16][3];     // per (b,f): [tsum, sum(tgtx), sum(tgty)]
__device__ uint2 g_meta[16][HH*3];     // per (b,f,row,chunk): {tmask bits, vpad bits}

__device__ __forceinline__ float sigmoid_fast(float x) {
    float a = fabsf(x);
    float u = __expf(-a);
    float r = __fdividef(1.0f, 1.0f + u);
    return (x >= 0.0f) ? r : u * r;
}

__device__ __forceinline__ float warp_sum(float v) {
    #pragma unroll
    for (int o = 16; o; o >>= 1) v += __shfl_xor_sync(0xffffffff, v, o);
    return v;
}
__device__ __forceinline__ float warp_max(float v) {
    #pragma unroll
    for (int o = 16; o; o >>= 1) v = fmaxf(v, __shfl_xor_sync(0xffffffff, v, o));
    return v;
}

// ---------------------------------------------------------------------------
// Prep: one block per (b,f). 384 threads = 12 warps; warp owns 8 rows.
// ---------------------------------------------------------------------------
__global__ __launch_bounds__(384) void prep_kernel(
    const float* __restrict__ tmask, const unsigned char* __restrict__ vpad)
{
    int bf = blockIdx.x;            // 0..15
    int b = bf >> 3, f = bf & 7;
    int tid = threadIdx.x;
    int wp = tid >> 5, lane = tid & 31;
    const float* base = tmask + (size_t)bf * HW;
    const unsigned char* vb = vpad + (size_t)b * HW;

    __shared__ float colPart[12][3][32];
    __shared__ float warpRM[12];
    __shared__ float warpTS[12];
    __shared__ float colFinal[96];

    float cm0 = -CUDART_INF_F, cm1 = -CUDART_INF_F, cm2 = -CUDART_INF_F;
    float rm_sum = 0.0f, t_sum = 0.0f;

    #pragma unroll
    for (int r = 0; r < 8; ++r) {
        int row = wp * 8 + r;
        const float* rp = base + row * WW;
        const unsigned char* vr = vb + row * WW;
        // hoist all 6 loads for MLP
        float v0 = rp[lane], v1 = rp[32 + lane], v2 = rp[64 + lane];
        unsigned char q0 = vr[lane], q1 = vr[32 + lane], q2 = vr[64 + lane];
        unsigned t0 = __ballot_sync(0xffffffff, v0 != 0.0f);
        unsigned t1 = __ballot_sync(0xffffffff, v1 != 0.0f);
        unsigned t2 = __ballot_sync(0xffffffff, v2 != 0.0f);
        unsigned p0 = __ballot_sync(0xffffffff, q0 != 0);
        unsigned p1 = __ballot_sync(0xffffffff, q1 != 0);
        unsigned p2 = __ballot_sync(0xffffffff, q2 != 0);
        if (lane == 0) {
            g_meta[bf][row * 3 + 0] = make_uint2(t0, p0);
            g_meta[bf][row * 3 + 1] = make_uint2(t1, p1);
            g_meta[bf][row * 3 + 2] = make_uint2(t2, p2);
        }
        float rm = warp_max(fmaxf(fmaxf(v0, v1), v2));
        if (lane == 0) { g_tgtx[b][f * HH + row] = rm; rm_sum += rm; }
        t_sum += v0 + v1 + v2;
        cm0 = fmaxf(cm0, v0); cm1 = fmaxf(cm1, v1); cm2 = fmaxf(cm2, v2);
    }
    colPart[wp][0][lane] = cm0;
    colPart[wp][1][lane] = cm1;
    colPart[wp][2][lane] = cm2;
    float ts = warp_sum(t_sum);
    if (lane == 0) { warpTS[wp] = ts; warpRM[wp] = rm_sum; }
    __syncthreads();

    if (tid < 96) {
        int c = tid >> 5, l = tid & 31;
        float m = -CUDART_INF_F;
        #pragma unroll
        for (int w = 0; w < 12; ++w) m = fmaxf(m, colPart[w][c][l]);
        g_tgty[b][f * WW + tid] = m;
        colFinal[tid] = m;
    }
    __syncthreads();
    if (tid == 0) {
        float tsum = 0, txs = 0, tys = 0;
        #pragma unroll
        for (int i = 0; i < 12; ++i) { tsum += warpTS[i]; txs += warpRM[i]; }
        for (int i = 0; i < 96; ++i) tys += colFinal[i];
        g_partial[bf][0] = tsum; g_partial[bf][1] = txs; g_partial[bf][2] = tys;
    }
}

// ---------------------------------------------------------------------------
// Main cost kernel: one block per (b, q). 384 threads = 12 warps.
// Warp wp owns rows 8*wp..8*wp+7 of every frame; lane l covers cols {l,32+l,64+l}.
// ---------------------------------------------------------------------------
__global__ __launch_bounds__(384, 3) void cost_kernel(
    const float* __restrict__ logits,   // (2,8,300,1)
    const float* __restrict__ boxes,    // (2,8,300,4)
    const float* __restrict__ masks,    // (2,8,300,96,96)
    const float* __restrict__ tbox,     // (2,8,4)
    const int*   __restrict__ tvalid,   // (2,8)
    float* __restrict__ C)              // (2,300)
{
    int blk = blockIdx.x;
    int b = blk / NQ, q = blk % NQ;
    int tid = threadIdx.x;
    int warp = tid >> 5, lane = tid & 31;

    __shared__ float rowFinal[NF * HH];           // 3 KB
    __shared__ float colAll[NF * 3 * 384];        // 36 KB: [f][chunk][warp][lane]
    __shared__ float red[12][7];

    float facc = 0.0f, nacc = 0.0f, sacc = 0.0f;

    for (int f = 0; f < NF; ++f) {
        const float* mb = masks + (size_t)((b * NF + f) * NQ + q) * HW + lane;
        const uint2* mt = g_meta[b * NF + f];
        float c0 = -CUDART_INF_F, c1 = -CUDART_INF_F, c2 = -CUDART_INF_F;
        #pragma unroll 2
        for (int r = 0; r < 8; ++r) {
            int row = warp * 8 + r;
            uint2 m0 = mt[row * 3 + 0];
            uint2 m1 = mt[row * 3 + 1];
            uint2 m2 = mt[row * 3 + 2];
            const float* rp = mb + row * WW;
            float x0 = rp[0], x1 = rp[32], x2 = rp[64];
            if ((m0.y >> lane) & 1) x0 = 0.0f;
            if ((m1.y >> lane) & 1) x1 = 0.0f;
            if ((m2.y >> lane) & 1) x2 = 0.0f;

            #pragma unroll
            for (int c = 0; c < 3; ++c) {
                float x = (c == 0) ? x0 : (c == 1) ? x1 : x2;
                unsigned tw = (c == 0) ? m0.x : (c == 1) ? m1.x : m2.x;
                bool tb = (tw >> lane) & 1;
                bool s = (x >= 0.0f);
                float u = __expf(-fabsf(x));
                float onep = 1.0f + u;
                float rr = __fdividef(1.0f, onep);
                float ur = u * rr;
                float p = s ? rr : ur;
                float lg = __logf(onep);
                float ce = fmaxf(tb ? -x : x, 0.0f) + lg;   // BCE
                float omp = (s == tb) ? ur : rr;            // 1 - p_t
                float at = tb ? 0.25f : 0.75f;
                facc = fmaf(at * ce * omp, omp, facc);
                sacc += p;
                if (tb) nacc += p;
            }
            c0 = fmaxf(c0, x0); c1 = fmaxf(c1, x1); c2 = fmaxf(c2, x2);
            float rm = warp_max(fmaxf(fmaxf(x0, x1), x2));
            if (lane == 0) rowFinal[f * HH + row] = rm;
        }
        colAll[((f * 3 + 0) * 12 + warp) * 32 + lane] = c0;
        colAll[((f * 3 + 1) * 12 + warp) * 32 + lane] = c1;
        colAll[((f * 3 + 2) * 12 + warp) * 32 + lane] = c2;
    }
    __syncthreads();

    // projection dice partials: 768 rows + 768 cols, 2 each per thread
    float sx = 0, nx = 0, sy = 0, ny = 0;
    #pragma unroll
    for (int j = tid; j < NF * HH; j += 384) {
        float px = sigmoid_fast(rowFinal[j]);
        sx += px; nx += px * g_tgtx[b][j];
        int f = j / WW, w = j % WW;
        int c = w >> 5, l = w & 31;
        const float* cp = &colAll[((f * 3 + c) * 12) * 32 + l];
        float m = cp[0];
        #pragma unroll
        for (int wp = 1; wp < 12; ++wp) m = fmaxf(m, cp[wp * 32]);
        float py = sigmoid_fast(m);
        sy += py; ny += py * g_tgty[b][j];
    }

    float v0 = warp_sum(facc), v1 = warp_sum(nacc), v2 = warp_sum(sacc);
    float v3 = warp_sum(sx),   v4 = warp_sum(nx);
    float v5 = warp_sum(sy),   v6 = warp_sum(ny);
    if (lane == 0) {
        red[warp][0] = v0; red[warp][1] = v1; red[warp][2] = v2;
        red[warp][3] = v3; red[warp][4] = v4; red[warp][5] = v5; red[warp][6] = v6;
    }
    __syncthreads();

    if (tid == 0) {
        float t0=0,t1=0,t2=0,t3=0,t4=0,t5=0,t6=0;
        #pragma unroll
        for (int i = 0; i < 12; ++i) {
            t0 += red[i][0]; t1 += red[i][1]; t2 += red[i][2];
            t3 += red[i][3]; t4 += red[i][4]; t5 += red[i][5]; t6 += red[i][6];
        }
        float tsum = 0, txs = 0, tys = 0;
        #pragma unroll
        for (int f = 0; f < NF; ++f) {
            tsum += g_partial[b * NF + f][0];
            txs  += g_partial[b * NF + f][1];
            tys  += g_partial[b * NF + f][2];
        }
        float cost_mask = t0 / (float)FHW;
        float cost_dice = -((2.0f * t1 + 1.0f) / (t2 + tsum + 1.0f));
        float dx = (2.0f * t4 + 1.0f) / (t3 + txs + 1.0f);
        float dy = (2.0f * t6 + 1.0f) / (t5 + tys + 1.0f);
        float cost_proj = -0.5f * (dy + dx);

        float cls = 0, wsum = 0, bbox = 0, giou = 0;
        #pragma unroll
        for (int f = 0; f < NF; ++f) {
            float lg = logits[(b * NF + f) * NQ + q];
            float p = sigmoid_fast(lg);
            float neg = (1.0f - ALPHA_C) * p * p * (-__logf(1.0f - p + EPSV));
            float pos = ALPHA_C * (1.0f - p) * (1.0f - p) * (-__logf(p + EPSV));
            float wv = (tvalid[b * NF + f] != 0) ? 1.0f : 0.0f;
            cls += (pos - neg) * wv; wsum += wv;

            const float* bx = boxes + (size_t)((b * NF + f) * NQ + q) * 4;
            const float* tx = tbox + (size_t)(b * NF + f) * 4;
            bbox += fabsf(bx[0]-tx[0]) + fabsf(bx[1]-tx[1]) + fabsf(bx[2]-tx[2]) + fabsf(bx[3]-tx[3]);

            float sx0 = bx[0]-0.5f*bx[2], sy0 = bx[1]-0.5f*bx[3];
            float sx1 = bx[0]+0.5f*bx[2], sy1 = bx[1]+0.5f*bx[3];
            float tx0 = tx[0]-0.5f*tx[2], ty0 = tx[1]-0.5f*tx[3];
            float tx1 = tx[0]+0.5f*tx[2], ty1 = tx[1]+0.5f*tx[3];
            float a1 = (sx1-sx0)*(sy1-sy0);
            float a2 = (tx1-tx0)*(ty1-ty0);
            float iw = fmaxf(fminf(sx1,tx1) - fmaxf(sx0,tx0), 0.0f);
            float ih = fmaxf(fminf(sy1,ty1) - fmaxf(sy0,ty0), 0.0f);
            float inter = iw * ih;
            float uni = a1 + a2 - inter;
            float iou = inter / uni;
            float cw = fmaxf(fmaxf(sx1,tx1) - fminf(sx0,tx0), 0.0f);
            float ch = fmaxf(fmaxf(sy1,ty1) - fminf(sy0,ty0), 0.0f);
            float ac = cw * ch;
            giou += -(iou - (ac - uni) / ac);
        }
        float cost_class = cls / wsum;
        float cost_bbox  = bbox * (1.0f / NF);
        float cost_giou  = giou * (1.0f / NF);

        C[b * NQ + q] = cost_class + cost_bbox + cost_giou + cost_mask + cost_dice + cost_proj;
    }
}

// ---------------------------------------------------------------------------
// Argmin over queries per batch + tail writes. grid=2, block=256
// ---------------------------------------------------------------------------
__global__ void argmin_kernel(const float* __restrict__ C, float* __restrict__ out, int out_size) {
    int b = blockIdx.x;
    int tid = threadIdx.x;
    float best = CUDART_INF_F; int bi = NQ;
    for (int q = tid; q < NQ; q += blockDim.x) {
        float v = C[b * NQ + q];
        if (v < best || (v == best && q < bi)) { best = v; bi = q; }
    }
    #pragma unroll
    for (int o = 16; o; o >>= 1) {
        float ov = __shfl_down_sync(0xffffffff, best, o);
        int   oi = __shfl_down_sync(0xffffffff, bi,   o);
        if (ov < best || (ov == best && oi < bi)) { best = ov; bi = oi; }
    }
    __shared__ float sv[8]; __shared__ int si[8];
    int wid = tid >> 5, lane = tid & 31;
    if (lane == 0) { sv[wid] = best; si[wid] = bi; }
    __syncthreads();
    if (tid == 0) {
        int nw = blockDim.x >> 5;
        for (int i = 1; i < nw; ++i) {
            if (sv[i] < best || (sv[i] == best && si[i] < bi)) { best = sv[i]; bi = si[i]; }
        }
        if (out_size >= 608) {
            long long* op = (long long*)(out + 600);
            op[b] = (long long)bi;
            op[2 + b] = 0ll;
            if (b == 0) for (int i = 608; i < out_size; ++i) out[i] = 0.0f;
        } else if (out_size >= 604) {
            out[600 + b] = (float)bi;
            out[602 + b] = 0.0f;
            if (b == 0) for (int i = 604; i < out_size; ++i) out[i] = 0.0f;
        } else {
            if (b == 0) for (int i = 600; i < out_size; ++i) out[i] = 0.0f;
        }
    }
}

extern "C" void kernel_launch(void* const* d_in, const int* in_sizes, int n_in,
                              void* d_out, int out_size) {
    const float* logits = (const float*)d_in[0];
    const float* boxes  = (const float*)d_in[1];
    const float* masks  = (const float*)d_in[2];
    const float* tmask  = (const float*)d_in[3];
    const float* tbox   = (const float*)d_in[4];
    const int*   tvalid = (const int*)d_in[5];
    const unsigned char* vpad = (const unsigned char*)d_in[6];
    float* out = (float*)d_out;

    prep_kernel<<<16, 384>>>(tmask, vpad);
    cost_kernel<<<2 * NQ, 384>>>(logits, boxes, masks, tbox, tvalid, out);
    argmin_kernel<<<2, 256>>>(out, out, out_size);
}